// round 1
// baseline (speedup 1.0000x reference)
#include <cuda_runtime.h>

// CASSI forward: out[b,l,i,j] = phi[i,j] * y2[b,i,2l+j]
// y2[b,i,k] = sum_{l'} x[b,l',i,k-2l'] * phi[i,k-2l']  (0 <= k-2l' < N)
//
// Shapes: x (B=8, L=28, M=512, N=512) f32, phi (512,512) f32, out same as x.
// One CTA per (b, i) row pair. HBM-bound: ~470 MB total traffic.

#define B_    8
#define L_    28
#define M_    512
#define N_    512
#define STRIDE_ 2
#define NOUT_ (N_ + STRIDE_ * (L_ - 1))   // 566
#define TPB   256

__global__ __launch_bounds__(TPB) void cassi_fused_kernel(
    const float* __restrict__ x,
    const float* __restrict__ phi,
    float* __restrict__ out)
{
    __shared__ float phi_s[N_];
    __shared__ float y2_s[NOUT_ + 2];   // +2 pad

    const int bm  = blockIdx.x;      // 0 .. B*M-1
    const int b   = bm / M_;
    const int i   = bm % M_;
    const int tid = threadIdx.x;

    // ---- load phi row i into smem (vectorized) ----
    {
        const float4* p4 = reinterpret_cast<const float4*>(phi + (size_t)i * N_);
        if (tid < N_ / 4) {
            reinterpret_cast<float4*>(phi_s)[tid] = p4[tid];
        }
    }
    __syncthreads();

    // base pointer to x[b, 0, i, 0]; band stride is M*N
    const float* xb = x + (size_t)b * (L_ * M_ * N_) + (size_t)i * N_;
    const size_t band_stride = (size_t)M_ * N_;

    // ---- compute y2 row: each thread owns up to 3 k-positions ----
    float acc0 = 0.f, acc1 = 0.f, acc2 = 0.f;
    {
        const int k0 = tid;
        const int k1 = tid + TPB;
        const int k2 = tid + 2 * TPB;

        #pragma unroll
        for (int l = 0; l < L_; ++l) {
            const float* xrow = xb + (size_t)l * band_stride;
            unsigned n0 = (unsigned)(k0 - STRIDE_ * l);
            unsigned n1 = (unsigned)(k1 - STRIDE_ * l);
            unsigned n2 = (unsigned)(k2 - STRIDE_ * l);
            if (n0 < N_) acc0 += xrow[n0] * phi_s[n0];
            if (n1 < N_) acc1 += xrow[n1] * phi_s[n1];
            if (n2 < N_) acc2 += xrow[n2] * phi_s[n2];
        }

        if (k0 < NOUT_) y2_s[k0] = acc0;
        if (k1 < NOUT_) y2_s[k1] = acc1;
        if (k2 < NOUT_) y2_s[k2] = acc2;
    }
    __syncthreads();

    // ---- epilogue: out[b,l,i,j] = phi_s[j] * y2_s[2l + j], float4 stores ----
    float* ob = out + (size_t)b * (L_ * M_ * N_) + (size_t)i * N_;
    const int QUADS_PER_ROW = N_ / 4;               // 128
    const int TOTAL_QUADS   = L_ * QUADS_PER_ROW;   // 3584

    #pragma unroll 4
    for (int q = tid; q < TOTAL_QUADS; q += TPB) {
        const int l   = q >> 7;            // q / 128
        const int qy  = q & (QUADS_PER_ROW - 1);
        const int j4  = qy * 4;
        const int base = STRIDE_ * l + j4; // even -> 8B aligned in y2_s

        float4 p = reinterpret_cast<const float4*>(phi_s)[qy];
        float4 r;
        r.x = p.x * y2_s[base + 0];
        r.y = p.y * y2_s[base + 1];
        r.z = p.z * y2_s[base + 2];
        r.w = p.w * y2_s[base + 3];
        reinterpret_cast<float4*>(ob + (size_t)l * band_stride)[qy] = r;
    }
}

extern "C" void kernel_launch(void* const* d_in, const int* in_sizes, int n_in,
                              void* d_out, int out_size)
{
    const float* x   = (const float*)d_in[0];
    const float* phi = (const float*)d_in[1];
    float* out       = (float*)d_out;

    cassi_fused_kernel<<<B_ * M_, TPB>>>(x, phi, out);
}